// round 14
// baseline (speedup 1.0000x reference)
#include <cuda_runtime.h>
#include <cstdint>
#include <cstddef>

#define BB 2
#define NP 16384
#define MP 8192
#define NR 128
#define KP 2048
#define HW 188
#define CB 256

// ---------------- device scratch (allocation-free) ----------------
__device__ float g_px[BB][3][NP];            // points xyz SoA
__device__ float g_d0[BB][NP];               // FPS init distances
__device__ float g_cx3[BB][3][MP];           // conv3 xyz SoA
__device__ float g_kp[BB][3][KP];            // keypoints SoA
__device__ float g_bevT[BB][HW][HW][CB];     // transposed BEV (B,H,W,C)
__device__ float g_fraw[BB][NP][32];         // relu(pfeat @ W_raw + b)
__device__ float g_gc3[BB][MP][64];          // relu(cfeat @ W_c3 + b)
__device__ float g_bevf[BB][KP][CB];         // bilinear features
__device__ float g_araw[BB][KP][32];         // raw aggregate sums
__device__ float g_craw[BB][KP];             // raw counts
__device__ float g_ac3[BB][KP][64];          // c3 aggregate sums
__device__ float g_cc3[BB][KP];              // c3 counts
// spatially-sorted copies for FPS (layout: slot = (pos&15)*1024 + (pos>>4))
__device__ float g_sx[BB][NP];
__device__ float g_sy[BB][NP];
__device__ float g_sz[BB][NP];
__device__ unsigned short g_sid[BB][NP];     // original index
__device__ float g_sd0[BB][NP];              // d0 in sorted layout

// exact f32: ((dx*dx + dy*dy) + dz*dz), no FMA contraction
__device__ __forceinline__ float sq_sum(float dx, float dy, float dz) {
    return __fadd_rn(__fadd_rn(__fmul_rn(dx, dx), __fmul_rn(dy, dy)), __fmul_rn(dz, dz));
}

// ---------------- 1. valid mask + d0 + xyz SoA ----------------
__global__ __launch_bounds__(256) void prep_points_kernel(const float* __restrict__ pts,
                                                          const float* __restrict__ bb) {
    __shared__ float rois[NR * 7];
    const int b = blockIdx.y;
    const int i = blockIdx.x * 256 + threadIdx.x;
    for (int r = threadIdx.x; r < NR * 7; r += 256) rois[r] = bb[b * NR * 7 + r];
    __syncthreads();
    const float* p = pts + ((size_t)(b * NP + i)) * 5;
    const float x = p[0], y = p[1], z = p[2];
    float mind = 3.4e38f;
    int mr = 0;
    #pragma unroll 4
    for (int r = 0; r < NR; r++) {
        float dx = __fsub_rn(x, rois[r * 7 + 0]);
        float dy = __fsub_rn(y, rois[r * 7 + 1]);
        float dz = __fsub_rn(z, rois[r * 7 + 2]);
        float dd = __fsqrt_rn(sq_sum(dx, dy, dz));
        if (dd < mind) { mind = dd; mr = r; }   // first occurrence on ties
    }
    const float hx = __fmul_rn(rois[mr * 7 + 3], 0.5f);
    const float hy = __fmul_rn(rois[mr * 7 + 4], 0.5f);
    const float hz = __fmul_rn(rois[mr * 7 + 5], 0.5f);
    const float rmax = __fsqrt_rn(sq_sum(hx, hy, hz));
    const bool valid = mind < __fadd_rn(rmax, 2.4f);
    g_px[b][0][i] = x;
    g_px[b][1][i] = y;
    g_px[b][2][i] = z;
    g_d0[b][i] = valid ? 1e10f : -1e10f;
}

// ---------------- 2. conv3 xyz SoA ----------------
__global__ __launch_bounds__(256) void prep_c3_kernel(const float* __restrict__ c3) {
    const int b = blockIdx.y;
    const int j = blockIdx.x * 256 + threadIdx.x;
    const float* p = c3 + ((size_t)(b * MP + j)) * 67;
    g_cx3[b][0][j] = p[0];
    g_cx3[b][1][j] = p[1];
    g_cx3[b][2][j] = p[2];
}

// ---------------- 2b. spatial counting sort (Morton, 32x32x2 cells) ----------------
__device__ __forceinline__ int part5(int v) {
    int r = 0;
    #pragma unroll
    for (int i = 0; i < 5; i++) r |= ((v >> i) & 1) << (2 * i);
    return r;
}

__global__ __launch_bounds__(1024) void sort_kernel() {
    __shared__ int hist[2048];
    __shared__ int wsum[32];
    const int b = blockIdx.x;
    const int t = threadIdx.x;
    const int lane = t & 31, wid = t >> 5;
    hist[t] = 0;
    hist[t + 1024] = 0;
    __syncthreads();
    int keys[16];
    #pragma unroll
    for (int k = 0; k < 16; k++) {
        const int i = t + k * 1024;
        const float x = g_px[b][0][i];
        const float y = g_px[b][1][i];
        const float z = g_px[b][2][i];
        int ix = (int)floorf((x + 75.2f) * (32.0f / 150.4f));
        int iy = (int)floorf((y + 75.2f) * (32.0f / 150.4f));
        ix = min(max(ix, 0), 31);
        iy = min(max(iy, 0), 31);
        const int iz = (z > 1.0f) ? 1 : 0;
        keys[k] = ((((part5(iy) << 1) | part5(ix)) << 1) | iz);
        atomicAdd(&hist[keys[k]], 1);
    }
    __syncthreads();
    // exclusive scan over 2048 counters (2 per thread)
    const int h0 = hist[2 * t], h1 = hist[2 * t + 1];
    const int s = h0 + h1;
    int v = s;
    #pragma unroll
    for (int off = 1; off < 32; off <<= 1) {
        const int n = __shfl_up_sync(0xffffffffu, v, off);
        if (lane >= off) v += n;
    }
    if (lane == 31) wsum[wid] = v;
    __syncthreads();
    if (wid == 0) {
        int w = wsum[lane];
        #pragma unroll
        for (int off = 1; off < 32; off <<= 1) {
            const int n = __shfl_up_sync(0xffffffffu, w, off);
            if (lane >= off) w += n;
        }
        wsum[lane] = w;
    }
    __syncthreads();
    const int base = (wid > 0 ? wsum[wid - 1] : 0) + (v - s);
    hist[2 * t] = base;
    hist[2 * t + 1] = base + h0;
    __syncthreads();
    #pragma unroll
    for (int k = 0; k < 16; k++) {
        const int i = t + k * 1024;
        const int pos = atomicAdd(&hist[keys[k]], 1);
        const int L = (pos & 15) * 1024 + (pos >> 4);
        g_sx[b][L] = g_px[b][0][i];
        g_sy[b][L] = g_px[b][1][i];
        g_sz[b][L] = g_px[b][2][i];
        g_sid[b][L] = (unsigned short)i;
        g_sd0[b][L] = g_d0[b][i];
    }
}

// ---------------- 3. FPS with tile pruning: one CTA per batch ----------------
// Thread t owns 16 spatially-contiguous sorted points at slots {k*1024+t}.
// Per-thread tile bound allows provably-no-op update skips (bit-exact result).
__global__ __launch_bounds__(1024, 1) void fps_kernel(float* __restrict__ out_kp) {
    extern __shared__ unsigned char smraw[];
    float* sx = (float*)smraw;
    float* sy = sx + NP;
    float* sz = sy + NP;
    float* s_val = sz + NP;
    int* s_key = (int*)(s_val + 32);
    float* s_bc = (float*)(s_key + 32);
    const int b = blockIdx.x;
    const int t = threadIdx.x;
    const int lane = t & 31, wid = t >> 5;

    float d[16];
    int key[16];
    float mnx = 3.4e38f, mxx = -3.4e38f;
    float mny = 3.4e38f, mxy = -3.4e38f;
    float mnz = 3.4e38f, mxz = -3.4e38f;
    #pragma unroll
    for (int k = 0; k < 16; k++) {
        const int slot = k * 1024 + t;
        const float x = g_sx[b][slot];
        const float y = g_sy[b][slot];
        const float z = g_sz[b][slot];
        sx[slot] = x; sy[slot] = y; sz[slot] = z;
        d[k] = g_sd0[b][slot];
        key[k] = (((int)g_sid[b][slot]) << 14) | slot;
        mnx = fminf(mnx, x); mxx = fmaxf(mxx, x);
        mny = fminf(mny, y); mxy = fmaxf(mxy, y);
        mnz = fminf(mnz, z); mxz = fmaxf(mxz, z);
    }
    const float tcx = (mnx + mxx) * 0.5f;
    const float tcy = (mny + mxy) * 0.5f;
    const float tcz = (mnz + mxz) * 0.5f;
    const float hx = (mxx - mnx) * 0.5f;
    const float hy = (mxy - mny) * 0.5f;
    const float hz = (mxz - mnz) * 0.5f;
    const float trad = sqrtf(hx * hx + hy * hy + hz * hz) * 1.0001f + 1e-3f;

    float tmax = -3.4e38f;
    int tkey = 0x7fffffff;
    #pragma unroll
    for (int k = 0; k < 16; k++) {
        if (d[k] > tmax || (d[k] == tmax && key[k] < tkey)) { tmax = d[k]; tkey = key[k]; }
    }
    __syncthreads();

    const bool wout = (out_kp != nullptr);
    for (int step = 0; step < KP; step++) {
        // block argmax over per-tile cached (max, key), min-key tie-break
        float m = tmax;
        int mk = tkey;
        #pragma unroll
        for (int off = 16; off; off >>= 1) {
            const float om = __shfl_down_sync(0xffffffffu, m, off);
            const int ok = __shfl_down_sync(0xffffffffu, mk, off);
            if (om > m || (om == m && ok < mk)) { m = om; mk = ok; }
        }
        if (lane == 0) { s_val[wid] = m; s_key[wid] = mk; }
        __syncthreads();
        if (wid == 0) {
            m = s_val[lane];
            mk = s_key[lane];
            #pragma unroll
            for (int off = 16; off; off >>= 1) {
                const float om = __shfl_down_sync(0xffffffffu, m, off);
                const int ok = __shfl_down_sync(0xffffffffu, mk, off);
                if (om > m || (om == m && ok < mk)) { m = om; mk = ok; }
            }
            if (lane == 0) {
                const int slot = mk & 16383;
                const float cx = sx[slot], cy = sy[slot], cz = sz[slot];
                s_bc[0] = cx; s_bc[1] = cy; s_bc[2] = cz;
                g_kp[b][0][step] = cx;
                g_kp[b][1][step] = cy;
                g_kp[b][2][step] = cz;
                if (wout) {
                    float* o = out_kp + ((size_t)b * KP + step) * 3;
                    o[0] = cx; o[1] = cy; o[2] = cz;
                }
            }
        }
        __syncthreads();
        const float cx = s_bc[0], cy = s_bc[1], cz = s_bc[2];
        // conservative prune: skip iff no point's min can change (bit-exact)
        const float ax = tcx - cx, ay = tcy - cy, az = tcz - cz;
        const float dcc = sqrtf(ax * ax + ay * ay + az * az);
        const float thr = trad + sqrtf(fmaxf(tmax, 0.0f)) + 1e-2f;
        if (dcc < thr) {
            float nm = -3.4e38f;
            int nk = 0x7fffffff;
            #pragma unroll
            for (int k = 0; k < 16; k++) {
                const int slot = k * 1024 + t;
                const float dx = __fsub_rn(sx[slot], cx);
                const float dy = __fsub_rn(sy[slot], cy);
                const float dz = __fsub_rn(sz[slot], cz);
                const float nd = sq_sum(dx, dy, dz);   // nd >= 0 keeps invalid at -1e10
                const float dn = fminf(d[k], nd);
                d[k] = dn;
                if (dn > nm || (dn == nm && key[k] < nk)) { nm = dn; nk = key[k]; }
            }
            tmax = nm;
            tkey = nk;
        }
    }
}

// ---------------- 4. BEV transpose (B,C,H,W) -> (B,H,W,C) ----------------
__global__ __launch_bounds__(256) void transpose_bev_kernel(const float* __restrict__ sp) {
    __shared__ float tile[32][33];
    const int x0 = blockIdx.x * 32;
    const int c0 = blockIdx.y * 32;
    const int byz = blockIdx.z;
    const int b = byz / HW, y = byz % HW;
    const int tx = threadIdx.x, ty = threadIdx.y;
    #pragma unroll
    for (int r = 0; r < 4; r++) {
        const int c = c0 + ty + r * 8;
        const int x = x0 + tx;
        float v = 0.f;
        if (x < HW) v = sp[(((size_t)b * CB + c) * HW + y) * HW + x];
        tile[ty + r * 8][tx] = v;
    }
    __syncthreads();
    #pragma unroll
    for (int r = 0; r < 4; r++) {
        const int x = x0 + ty + r * 8;
        const int c = c0 + tx;
        if (x < HW) g_bevT[b][y][x][c] = tile[tx][ty + r * 8];
    }
}

// ---------------- 5. raw point feature transform ----------------
__global__ __launch_bounds__(256) void transform_raw_kernel(const float* __restrict__ pts,
                                                            const float* __restrict__ Wr,
                                                            const float* __restrict__ br) {
    const int b = blockIdx.y;
    const int t = threadIdx.x;
    const int pt = blockIdx.x * 8 + (t >> 5);
    const int k = t & 31;
    const float* p = pts + ((size_t)(b * NP + pt)) * 5;
    const float f = fmaf(p[3], Wr[k], fmaf(p[4], Wr[32 + k], br[k]));
    g_fraw[b][pt][k] = fmaxf(f, 0.f);
}

// ---------------- 6. conv3 feature transform ----------------
__global__ __launch_bounds__(256) void transform_c3_kernel(const float* __restrict__ c3,
                                                           const float* __restrict__ Wc,
                                                           const float* __restrict__ bc) {
    __shared__ float sf[4][64];
    const int b = blockIdx.y;
    const int row0 = blockIdx.x * 4;
    const int t = threadIdx.x;
    const int r = t >> 6, o = t & 63;
    sf[r][o] = c3[((size_t)(b * MP + row0 + r)) * 67 + 3 + o];
    __syncthreads();
    float s = bc[o];
    #pragma unroll 8
    for (int c = 0; c < 64; c++) s = fmaf(sf[r][c], Wc[c * 64 + o], s);
    g_gc3[b][row0 + r][o] = fmaxf(s, 0.f);
}

// ---------------- 7. bilinear BEV sampling ----------------
__global__ __launch_bounds__(256) void bilinear_kernel() {
    const int k = blockIdx.x, b = blockIdx.y, c = threadIdx.x;
    const float kx = g_kp[b][0][k];
    const float ky = g_kp[b][1][k];
    const float xi = __fdiv_rn(__fdiv_rn(__fsub_rn(kx, -75.2f), 0.1f), 8.0f);
    const float yi = __fdiv_rn(__fdiv_rn(__fsub_rn(ky, -75.2f), 0.1f), 8.0f);
    int x0 = (int)floorf(xi);
    x0 = min(max(x0, 0), HW - 1);
    const int x1 = min(x0 + 1, HW - 1);
    int y0 = (int)floorf(yi);
    y0 = min(max(y0, 0), HW - 1);
    const int y1 = min(y0 + 1, HW - 1);
    const float xf0 = (float)x0, xf1 = (float)x1;
    const float yf0 = (float)y0, yf1 = (float)y1;
    const float wa = __fmul_rn(__fsub_rn(xf1, xi), __fsub_rn(yf1, yi));
    const float wb = __fmul_rn(__fsub_rn(xf1, xi), __fsub_rn(yi, yf0));
    const float wc = __fmul_rn(__fsub_rn(xi, xf0), __fsub_rn(yf1, yi));
    const float wd = __fmul_rn(__fsub_rn(xi, xf0), __fsub_rn(yi, yf0));
    const float* base = &g_bevT[b][0][0][0];
    const float Ia = base[((size_t)(y0 * HW + x0)) * CB + c];
    const float Ib = base[((size_t)(y1 * HW + x0)) * CB + c];
    const float Ic = base[((size_t)(y0 * HW + x1)) * CB + c];
    const float Id = base[((size_t)(y1 * HW + x1)) * CB + c];
    g_bevf[b][k][c] = fmaf(Id, wd, fmaf(Ic, wc, fmaf(Ib, wb, Ia * wa)));
}

// ---------------- 8. raw aggregation (one warp per keypoint) ----------------
__global__ __launch_bounds__(256) void agg_raw_kernel() {
    const int lane = threadIdx.x & 31;
    const int wid = threadIdx.x >> 5;
    const int g = blockIdx.x * 8 + wid;
    const int b = g >> 11;
    const int k = g & (KP - 1);
    const float kx = g_kp[b][0][k], ky = g_kp[b][1][k], kz = g_kp[b][2][k];
    const float R2 = (float)(0.8 * 0.8);  // f64 product, then f32 (matches JAX weak type)
    float acc[32];
    #pragma unroll
    for (int i = 0; i < 32; i++) acc[i] = 0.f;
    int cnt = 0;
    for (int j = lane; j < NP; j += 32) {
        const float dx = __fsub_rn(kx, g_px[b][0][j]);
        const float dy = __fsub_rn(ky, g_px[b][1][j]);
        const float dz = __fsub_rn(kz, g_px[b][2][j]);
        const float d2 = sq_sum(dx, dy, dz);
        if (d2 < R2) {
            cnt++;
            const float4* fp = reinterpret_cast<const float4*>(g_fraw[b][j]);
            #pragma unroll
            for (int q = 0; q < 8; q++) {
                const float4 v = fp[q];
                acc[4 * q + 0] += v.x;
                acc[4 * q + 1] += v.y;
                acc[4 * q + 2] += v.z;
                acc[4 * q + 3] += v.w;
            }
        }
    }
    float cf = (float)cnt;
    #pragma unroll
    for (int off = 16; off; off >>= 1) cf += __shfl_xor_sync(0xffffffffu, cf, off);
    float mine = 0.f;
    #pragma unroll
    for (int i = 0; i < 32; i++) {
        float v = acc[i];
        #pragma unroll
        for (int off = 16; off; off >>= 1) v += __shfl_xor_sync(0xffffffffu, v, off);
        if (lane == i) mine = v;
    }
    g_araw[b][k][lane] = mine;
    if (lane == 0) g_craw[b][k] = cf;
}

// ---------------- 9. conv3 aggregation ----------------
__global__ __launch_bounds__(256) void agg_c3_kernel() {
    const int lane = threadIdx.x & 31;
    const int wid = threadIdx.x >> 5;
    const int g = blockIdx.x * 8 + wid;
    const int b = g >> 11;
    const int k = g & (KP - 1);
    const float kx = g_kp[b][0][k], ky = g_kp[b][1][k], kz = g_kp[b][2][k];
    const float R2 = (float)(1.6 * 1.6);
    float acc[64];
    #pragma unroll
    for (int i = 0; i < 64; i++) acc[i] = 0.f;
    int cnt = 0;
    for (int j = lane; j < MP; j += 32) {
        const float dx = __fsub_rn(kx, g_cx3[b][0][j]);
        const float dy = __fsub_rn(ky, g_cx3[b][1][j]);
        const float dz = __fsub_rn(kz, g_cx3[b][2][j]);
        const float d2 = sq_sum(dx, dy, dz);
        if (d2 < R2) {
            cnt++;
            const float4* fp = reinterpret_cast<const float4*>(g_gc3[b][j]);
            #pragma unroll
            for (int q = 0; q < 16; q++) {
                const float4 v = fp[q];
                acc[4 * q + 0] += v.x;
                acc[4 * q + 1] += v.y;
                acc[4 * q + 2] += v.z;
                acc[4 * q + 3] += v.w;
            }
        }
    }
    float cf = (float)cnt;
    #pragma unroll
    for (int off = 16; off; off >>= 1) cf += __shfl_xor_sync(0xffffffffu, cf, off);
    float mine0 = 0.f, mine1 = 0.f;
    #pragma unroll
    for (int i = 0; i < 32; i++) {
        float v = acc[i];
        #pragma unroll
        for (int off = 16; off; off >>= 1) v += __shfl_xor_sync(0xffffffffu, v, off);
        if (lane == i) mine0 = v;
    }
    #pragma unroll
    for (int i = 32; i < 64; i++) {
        float v = acc[i];
        #pragma unroll
        for (int off = 16; off; off >>= 1) v += __shfl_xor_sync(0xffffffffu, v, off);
        if (lane == i - 32) mine1 = v;
    }
    g_ac3[b][k][lane] = mine0;
    g_ac3[b][k][32 + lane] = mine1;
    if (lane == 0) g_cc3[b][k] = cf;
}

// ---------------- 10. fuse: concat -> GEMV -> BN -> relu ----------------
__global__ __launch_bounds__(128) void fuse_kernel(const float* __restrict__ Wf,
                                                   const float* __restrict__ gma,
                                                   const float* __restrict__ bta,
                                                   const float* __restrict__ mea,
                                                   const float* __restrict__ var,
                                                   float* __restrict__ out) {
    __shared__ float f[352];
    const int k = blockIdx.x, b = blockIdx.y, t = threadIdx.x;
    f[t] = g_bevf[b][k][t];
    f[128 + t] = g_bevf[b][k][128 + t];
    if (t < 32) {
        const float c = fmaxf(g_craw[b][k], 1.0f);
        f[256 + t] = __fdiv_rn(g_araw[b][k][t], c);
    } else if (t < 96) {
        const float c = fmaxf(g_cc3[b][k], 1.0f);
        f[256 + t] = __fdiv_rn(g_ac3[b][k][t - 32], c);
    }
    __syncthreads();
    float s = 0.f;
    #pragma unroll 8
    for (int c = 0; c < 352; c++) s = fmaf(f[c], Wf[c * 128 + t], s);
    const float bn = (s - mea[t]) * rsqrtf(var[t] + 1e-5f) * gma[t] + bta[t];
    out[((size_t)(b * KP + k)) * 128 + t] = fmaxf(bn, 0.f);
}

// ---------------- launcher ----------------
extern "C" void kernel_launch(void* const* d_in, const int* in_sizes, int n_in,
                              void* d_out, int out_size) {
    const float* points  = (const float*)d_in[0];
    const float* bboxes  = (const float*)d_in[1];
    const float* spatial = (const float*)d_in[2];
    const float* conv3   = (const float*)d_in[3];
    const float* W_raw   = (const float*)d_in[4];
    const float* b_raw   = (const float*)d_in[5];
    const float* W_c3    = (const float*)d_in[6];
    const float* b_c3    = (const float*)d_in[7];
    const float* W_fuse  = (const float*)d_in[8];
    const float* bn_g    = (const float*)d_in[9];
    const float* bn_b    = (const float*)d_in[10];
    const float* bn_m    = (const float*)d_in[11];
    const float* bn_v    = (const float*)d_in[12];
    float* out = (float*)d_out;

    const int main_elems = BB * KP * 128;
    float* out_kp = nullptr;
    if (out_size >= main_elems + BB * KP * 3) out_kp = out + (out_size - BB * KP * 3);

    const int fps_smem = 3 * NP * (int)sizeof(float) + 32 * 4 + 32 * 4 + 4 * 4;
    cudaFuncSetAttribute(fps_kernel, cudaFuncAttributeMaxDynamicSharedMemorySize, fps_smem);

    prep_points_kernel<<<dim3(NP / 256, BB), 256>>>(points, bboxes);
    sort_kernel<<<BB, 1024>>>();
    fps_kernel<<<BB, 1024, fps_smem>>>(out_kp);
    prep_c3_kernel<<<dim3(MP / 256, BB), 256>>>(conv3);
    transform_raw_kernel<<<dim3(NP / 8, BB), 256>>>(points, W_raw, b_raw);
    transform_c3_kernel<<<dim3(MP / 4, BB), 256>>>(conv3, W_c3, b_c3);
    transpose_bev_kernel<<<dim3((HW + 31) / 32, CB / 32, BB * HW), dim3(32, 8)>>>(spatial);
    bilinear_kernel<<<dim3(KP, BB), 256>>>();
    agg_raw_kernel<<<dim3(BB * KP / 8), 256>>>();
    agg_c3_kernel<<<dim3(BB * KP / 8), 256>>>();
    fuse_kernel<<<dim3(KP, BB), 128>>>(W_fuse, bn_g, bn_b, bn_m, bn_v, out);
}

// round 15
// speedup vs baseline: 1.0511x; 1.0511x over previous
#include <cuda_runtime.h>
#include <cstdint>
#include <cstddef>

#define BB 2
#define NP 16384
#define MP 8192
#define NR 128
#define KP 2048
#define HW 188
#define CB 256

// ---------------- device scratch (allocation-free) ----------------
__device__ float g_px[BB][3][NP];            // points xyz SoA
__device__ float g_d0[BB][NP];               // FPS init distances
__device__ float g_cx3[BB][3][MP];           // conv3 xyz SoA
__device__ float g_kp[BB][3][KP];            // keypoints SoA
__device__ float g_bevT[BB][HW][HW][CB];     // transposed BEV (B,H,W,C)
__device__ float g_fraw[BB][NP][32];         // relu(pfeat @ W_raw + b)
__device__ float g_gc3[BB][MP][64];          // relu(cfeat @ W_c3 + b)
__device__ float g_bevf[BB][KP][CB];         // bilinear features
__device__ float g_araw[BB][KP][32];         // raw aggregate sums
__device__ float g_craw[BB][KP];             // raw counts
__device__ float g_ac3[BB][KP][64];          // c3 aggregate sums
__device__ float g_cc3[BB][KP];              // c3 counts
// spatially-sorted copies for FPS (layout: slot = (pos&15)*1024 + (pos>>4))
__device__ float g_sx[BB][NP];
__device__ float g_sy[BB][NP];
__device__ float g_sz[BB][NP];
__device__ unsigned short g_sid[BB][NP];     // original index
__device__ float g_sd0[BB][NP];              // d0 in sorted layout

// exact f32: ((dx*dx + dy*dy) + dz*dz), no FMA contraction
__device__ __forceinline__ float sq_sum(float dx, float dy, float dz) {
    return __fadd_rn(__fadd_rn(__fmul_rn(dx, dx), __fmul_rn(dy, dy)), __fmul_rn(dz, dz));
}

// ---------------- 1. valid mask + d0 + xyz SoA ----------------
__global__ __launch_bounds__(256) void prep_points_kernel(const float* __restrict__ pts,
                                                          const float* __restrict__ bb) {
    __shared__ float rois[NR * 7];
    const int b = blockIdx.y;
    const int i = blockIdx.x * 256 + threadIdx.x;
    for (int r = threadIdx.x; r < NR * 7; r += 256) rois[r] = bb[b * NR * 7 + r];
    __syncthreads();
    const float* p = pts + ((size_t)(b * NP + i)) * 5;
    const float x = p[0], y = p[1], z = p[2];
    float mind = 3.4e38f;
    int mr = 0;
    #pragma unroll 4
    for (int r = 0; r < NR; r++) {
        float dx = __fsub_rn(x, rois[r * 7 + 0]);
        float dy = __fsub_rn(y, rois[r * 7 + 1]);
        float dz = __fsub_rn(z, rois[r * 7 + 2]);
        float dd = __fsqrt_rn(sq_sum(dx, dy, dz));
        if (dd < mind) { mind = dd; mr = r; }   // first occurrence on ties
    }
    const float hx = __fmul_rn(rois[mr * 7 + 3], 0.5f);
    const float hy = __fmul_rn(rois[mr * 7 + 4], 0.5f);
    const float hz = __fmul_rn(rois[mr * 7 + 5], 0.5f);
    const float rmax = __fsqrt_rn(sq_sum(hx, hy, hz));
    const bool valid = mind < __fadd_rn(rmax, 2.4f);
    g_px[b][0][i] = x;
    g_px[b][1][i] = y;
    g_px[b][2][i] = z;
    g_d0[b][i] = valid ? 1e10f : -1e10f;
}

// ---------------- 2. conv3 xyz SoA ----------------
__global__ __launch_bounds__(256) void prep_c3_kernel(const float* __restrict__ c3) {
    const int b = blockIdx.y;
    const int j = blockIdx.x * 256 + threadIdx.x;
    const float* p = c3 + ((size_t)(b * MP + j)) * 67;
    g_cx3[b][0][j] = p[0];
    g_cx3[b][1][j] = p[1];
    g_cx3[b][2][j] = p[2];
}

// ---------------- 2b. spatial counting sort (Morton, 32x32x2 cells) ----------------
__device__ __forceinline__ int part5(int v) {
    int r = 0;
    #pragma unroll
    for (int i = 0; i < 5; i++) r |= ((v >> i) & 1) << (2 * i);
    return r;
}

__global__ __launch_bounds__(1024) void sort_kernel() {
    __shared__ int hist[2048];
    __shared__ int wsum[32];
    const int b = blockIdx.x;
    const int t = threadIdx.x;
    const int lane = t & 31, wid = t >> 5;
    hist[t] = 0;
    hist[t + 1024] = 0;
    __syncthreads();
    int keys[16];
    #pragma unroll
    for (int k = 0; k < 16; k++) {
        const int i = t + k * 1024;
        const float x = g_px[b][0][i];
        const float y = g_px[b][1][i];
        const float z = g_px[b][2][i];
        int ix = (int)floorf((x + 75.2f) * (32.0f / 150.4f));
        int iy = (int)floorf((y + 75.2f) * (32.0f / 150.4f));
        ix = min(max(ix, 0), 31);
        iy = min(max(iy, 0), 31);
        const int iz = (z > 1.0f) ? 1 : 0;
        keys[k] = ((((part5(iy) << 1) | part5(ix)) << 1) | iz);
        atomicAdd(&hist[keys[k]], 1);
    }
    __syncthreads();
    // exclusive scan over 2048 counters (2 per thread)
    const int h0 = hist[2 * t], h1 = hist[2 * t + 1];
    const int s = h0 + h1;
    int v = s;
    #pragma unroll
    for (int off = 1; off < 32; off <<= 1) {
        const int n = __shfl_up_sync(0xffffffffu, v, off);
        if (lane >= off) v += n;
    }
    if (lane == 31) wsum[wid] = v;
    __syncthreads();
    if (wid == 0) {
        int w = wsum[lane];
        #pragma unroll
        for (int off = 1; off < 32; off <<= 1) {
            const int n = __shfl_up_sync(0xffffffffu, w, off);
            if (lane >= off) w += n;
        }
        wsum[lane] = w;
    }
    __syncthreads();
    const int base = (wid > 0 ? wsum[wid - 1] : 0) + (v - s);
    hist[2 * t] = base;
    hist[2 * t + 1] = base + h0;
    __syncthreads();
    #pragma unroll
    for (int k = 0; k < 16; k++) {
        const int i = t + k * 1024;
        const int pos = atomicAdd(&hist[keys[k]], 1);
        const int L = (pos & 15) * 1024 + (pos >> 4);
        g_sx[b][L] = g_px[b][0][i];
        g_sy[b][L] = g_px[b][1][i];
        g_sz[b][L] = g_px[b][2][i];
        g_sid[b][L] = (unsigned short)i;
        g_sd0[b][L] = g_d0[b][i];
    }
}

// ---------------- 3. FPS with tile pruning: one CTA per batch ----------------
// Thread t owns 16 spatially-contiguous sorted points at slots {k*1024+t}.
// Per-thread tile bound allows provably-no-op update skips (bit-exact result).
__global__ __launch_bounds__(1024, 1) void fps_kernel(float* __restrict__ out_kp) {
    extern __shared__ unsigned char smraw[];
    float* sx = (float*)smraw;
    float* sy = sx + NP;
    float* sz = sy + NP;
    float* s_val = sz + NP;
    int* s_key = (int*)(s_val + 32);
    float* s_bc = (float*)(s_key + 32);
    const int b = blockIdx.x;
    const int t = threadIdx.x;
    const int lane = t & 31, wid = t >> 5;

    float d[16];
    int key[16];
    float mnx = 3.4e38f, mxx = -3.4e38f;
    float mny = 3.4e38f, mxy = -3.4e38f;
    float mnz = 3.4e38f, mxz = -3.4e38f;
    #pragma unroll
    for (int k = 0; k < 16; k++) {
        const int slot = k * 1024 + t;
        const float x = g_sx[b][slot];
        const float y = g_sy[b][slot];
        const float z = g_sz[b][slot];
        sx[slot] = x; sy[slot] = y; sz[slot] = z;
        d[k] = g_sd0[b][slot];
        key[k] = (((int)g_sid[b][slot]) << 14) | slot;
        mnx = fminf(mnx, x); mxx = fmaxf(mxx, x);
        mny = fminf(mny, y); mxy = fmaxf(mxy, y);
        mnz = fminf(mnz, z); mxz = fmaxf(mxz, z);
    }
    const float tcx = (mnx + mxx) * 0.5f;
    const float tcy = (mny + mxy) * 0.5f;
    const float tcz = (mnz + mxz) * 0.5f;
    const float hx = (mxx - mnx) * 0.5f;
    const float hy = (mxy - mny) * 0.5f;
    const float hz = (mxz - mnz) * 0.5f;
    const float trad = sqrtf(hx * hx + hy * hy + hz * hz) * 1.0001f + 1e-3f;

    float tmax = -3.4e38f;
    int tkey = 0x7fffffff;
    #pragma unroll
    for (int k = 0; k < 16; k++) {
        if (d[k] > tmax || (d[k] == tmax && key[k] < tkey)) { tmax = d[k]; tkey = key[k]; }
    }
    __syncthreads();

    const bool wout = (out_kp != nullptr);
    for (int step = 0; step < KP; step++) {
        // block argmax over per-tile cached (max, key), min-key tie-break
        float m = tmax;
        int mk = tkey;
        #pragma unroll
        for (int off = 16; off; off >>= 1) {
            const float om = __shfl_down_sync(0xffffffffu, m, off);
            const int ok = __shfl_down_sync(0xffffffffu, mk, off);
            if (om > m || (om == m && ok < mk)) { m = om; mk = ok; }
        }
        if (lane == 0) { s_val[wid] = m; s_key[wid] = mk; }
        __syncthreads();
        if (wid == 0) {
            m = s_val[lane];
            mk = s_key[lane];
            #pragma unroll
            for (int off = 16; off; off >>= 1) {
                const float om = __shfl_down_sync(0xffffffffu, m, off);
                const int ok = __shfl_down_sync(0xffffffffu, mk, off);
                if (om > m || (om == m && ok < mk)) { m = om; mk = ok; }
            }
            if (lane == 0) {
                const int slot = mk & 16383;
                const float cx = sx[slot], cy = sy[slot], cz = sz[slot];
                s_bc[0] = cx; s_bc[1] = cy; s_bc[2] = cz;
                g_kp[b][0][step] = cx;
                g_kp[b][1][step] = cy;
                g_kp[b][2][step] = cz;
                if (wout) {
                    float* o = out_kp + ((size_t)b * KP + step) * 3;
                    o[0] = cx; o[1] = cy; o[2] = cz;
                }
            }
        }
        __syncthreads();
        const float cx = s_bc[0], cy = s_bc[1], cz = s_bc[2];
        // conservative prune: skip iff no point's min can change (bit-exact)
        const float ax = tcx - cx, ay = tcy - cy, az = tcz - cz;
        const float dcc = sqrtf(ax * ax + ay * ay + az * az);
        const float thr = trad + sqrtf(fmaxf(tmax, 0.0f)) + 1e-2f;
        if (dcc < thr) {
            float nm = -3.4e38f;
            int nk = 0x7fffffff;
            #pragma unroll
            for (int k = 0; k < 16; k++) {
                const int slot = k * 1024 + t;
                const float dx = __fsub_rn(sx[slot], cx);
                const float dy = __fsub_rn(sy[slot], cy);
                const float dz = __fsub_rn(sz[slot], cz);
                const float nd = sq_sum(dx, dy, dz);   // nd >= 0 keeps invalid at -1e10
                const float dn = fminf(d[k], nd);
                d[k] = dn;
                if (dn > nm || (dn == nm && key[k] < nk)) { nm = dn; nk = key[k]; }
            }
            tmax = nm;
            tkey = nk;
        }
    }
}

// ---------------- 4. BEV transpose (B,C,H,W) -> (B,H,W,C) ----------------
__global__ __launch_bounds__(256) void transpose_bev_kernel(const float* __restrict__ sp) {
    __shared__ float tile[32][33];
    const int x0 = blockIdx.x * 32;
    const int c0 = blockIdx.y * 32;
    const int byz = blockIdx.z;
    const int b = byz / HW, y = byz % HW;
    const int tx = threadIdx.x, ty = threadIdx.y;
    #pragma unroll
    for (int r = 0; r < 4; r++) {
        const int c = c0 + ty + r * 8;
        const int x = x0 + tx;
        float v = 0.f;
        if (x < HW) v = sp[(((size_t)b * CB + c) * HW + y) * HW + x];
        tile[ty + r * 8][tx] = v;
    }
    __syncthreads();
    #pragma unroll
    for (int r = 0; r < 4; r++) {
        const int x = x0 + ty + r * 8;
        const int c = c0 + tx;
        if (x < HW) g_bevT[b][y][x][c] = tile[tx][ty + r * 8];
    }
}

// ---------------- 5. raw point feature transform ----------------
__global__ __launch_bounds__(256) void transform_raw_kernel(const float* __restrict__ pts,
                                                            const float* __restrict__ Wr,
                                                            const float* __restrict__ br) {
    const int b = blockIdx.y;
    const int t = threadIdx.x;
    const int pt = blockIdx.x * 8 + (t >> 5);
    const int k = t & 31;
    const float* p = pts + ((size_t)(b * NP + pt)) * 5;
    const float f = fmaf(p[3], Wr[k], fmaf(p[4], Wr[32 + k], br[k]));
    g_fraw[b][pt][k] = fmaxf(f, 0.f);
}

// ---------------- 6. conv3 feature transform ----------------
__global__ __launch_bounds__(256) void transform_c3_kernel(const float* __restrict__ c3,
                                                           const float* __restrict__ Wc,
                                                           const float* __restrict__ bc) {
    __shared__ float sf[4][64];
    const int b = blockIdx.y;
    const int row0 = blockIdx.x * 4;
    const int t = threadIdx.x;
    const int r = t >> 6, o = t & 63;
    sf[r][o] = c3[((size_t)(b * MP + row0 + r)) * 67 + 3 + o];
    __syncthreads();
    float s = bc[o];
    #pragma unroll 8
    for (int c = 0; c < 64; c++) s = fmaf(sf[r][c], Wc[c * 64 + o], s);
    g_gc3[b][row0 + r][o] = fmaxf(s, 0.f);
}

// ---------------- 7. bilinear BEV sampling ----------------
__global__ __launch_bounds__(256) void bilinear_kernel() {
    const int k = blockIdx.x, b = blockIdx.y, c = threadIdx.x;
    const float kx = g_kp[b][0][k];
    const float ky = g_kp[b][1][k];
    const float xi = __fdiv_rn(__fdiv_rn(__fsub_rn(kx, -75.2f), 0.1f), 8.0f);
    const float yi = __fdiv_rn(__fdiv_rn(__fsub_rn(ky, -75.2f), 0.1f), 8.0f);
    int x0 = (int)floorf(xi);
    x0 = min(max(x0, 0), HW - 1);
    const int x1 = min(x0 + 1, HW - 1);
    int y0 = (int)floorf(yi);
    y0 = min(max(y0, 0), HW - 1);
    const int y1 = min(y0 + 1, HW - 1);
    const float xf0 = (float)x0, xf1 = (float)x1;
    const float yf0 = (float)y0, yf1 = (float)y1;
    const float wa = __fmul_rn(__fsub_rn(xf1, xi), __fsub_rn(yf1, yi));
    const float wb = __fmul_rn(__fsub_rn(xf1, xi), __fsub_rn(yi, yf0));
    const float wc = __fmul_rn(__fsub_rn(xi, xf0), __fsub_rn(yf1, yi));
    const float wd = __fmul_rn(__fsub_rn(xi, xf0), __fsub_rn(yi, yf0));
    const float* base = &g_bevT[b][0][0][0];
    const float Ia = base[((size_t)(y0 * HW + x0)) * CB + c];
    const float Ib = base[((size_t)(y1 * HW + x0)) * CB + c];
    const float Ic = base[((size_t)(y0 * HW + x1)) * CB + c];
    const float Id = base[((size_t)(y1 * HW + x1)) * CB + c];
    g_bevf[b][k][c] = fmaf(Id, wd, fmaf(Ic, wc, fmaf(Ib, wb, Ia * wa)));
}

// ---------------- 8. raw aggregation (one warp per keypoint) ----------------
__global__ __launch_bounds__(256) void agg_raw_kernel() {
    const int lane = threadIdx.x & 31;
    const int wid = threadIdx.x >> 5;
    const int g = blockIdx.x * 8 + wid;
    const int b = g >> 11;
    const int k = g & (KP - 1);
    const float kx = g_kp[b][0][k], ky = g_kp[b][1][k], kz = g_kp[b][2][k];
    const float R2 = (float)(0.8 * 0.8);  // f64 product, then f32 (matches JAX weak type)
    float acc[32];
    #pragma unroll
    for (int i = 0; i < 32; i++) acc[i] = 0.f;
    int cnt = 0;
    for (int j = lane; j < NP; j += 32) {
        const float dx = __fsub_rn(kx, g_px[b][0][j]);
        const float dy = __fsub_rn(ky, g_px[b][1][j]);
        const float dz = __fsub_rn(kz, g_px[b][2][j]);
        const float d2 = sq_sum(dx, dy, dz);
        if (d2 < R2) {
            cnt++;
            const float4* fp = reinterpret_cast<const float4*>(g_fraw[b][j]);
            #pragma unroll
            for (int q = 0; q < 8; q++) {
                const float4 v = fp[q];
                acc[4 * q + 0] += v.x;
                acc[4 * q + 1] += v.y;
                acc[4 * q + 2] += v.z;
                acc[4 * q + 3] += v.w;
            }
        }
    }
    float cf = (float)cnt;
    #pragma unroll
    for (int off = 16; off; off >>= 1) cf += __shfl_xor_sync(0xffffffffu, cf, off);
    float mine = 0.f;
    #pragma unroll
    for (int i = 0; i < 32; i++) {
        float v = acc[i];
        #pragma unroll
        for (int off = 16; off; off >>= 1) v += __shfl_xor_sync(0xffffffffu, v, off);
        if (lane == i) mine = v;
    }
    g_araw[b][k][lane] = mine;
    if (lane == 0) g_craw[b][k] = cf;
}

// ---------------- 9. conv3 aggregation ----------------
__global__ __launch_bounds__(256) void agg_c3_kernel() {
    const int lane = threadIdx.x & 31;
    const int wid = threadIdx.x >> 5;
    const int g = blockIdx.x * 8 + wid;
    const int b = g >> 11;
    const int k = g & (KP - 1);
    const float kx = g_kp[b][0][k], ky = g_kp[b][1][k], kz = g_kp[b][2][k];
    const float R2 = (float)(1.6 * 1.6);
    float acc[64];
    #pragma unroll
    for (int i = 0; i < 64; i++) acc[i] = 0.f;
    int cnt = 0;
    for (int j = lane; j < MP; j += 32) {
        const float dx = __fsub_rn(kx, g_cx3[b][0][j]);
        const float dy = __fsub_rn(ky, g_cx3[b][1][j]);
        const float dz = __fsub_rn(kz, g_cx3[b][2][j]);
        const float d2 = sq_sum(dx, dy, dz);
        if (d2 < R2) {
            cnt++;
            const float4* fp = reinterpret_cast<const float4*>(g_gc3[b][j]);
            #pragma unroll
            for (int q = 0; q < 16; q++) {
                const float4 v = fp[q];
                acc[4 * q + 0] += v.x;
                acc[4 * q + 1] += v.y;
                acc[4 * q + 2] += v.z;
                acc[4 * q + 3] += v.w;
            }
        }
    }
    float cf = (float)cnt;
    #pragma unroll
    for (int off = 16; off; off >>= 1) cf += __shfl_xor_sync(0xffffffffu, cf, off);
    float mine0 = 0.f, mine1 = 0.f;
    #pragma unroll
    for (int i = 0; i < 32; i++) {
        float v = acc[i];
        #pragma unroll
        for (int off = 16; off; off >>= 1) v += __shfl_xor_sync(0xffffffffu, v, off);
        if (lane == i) mine0 = v;
    }
    #pragma unroll
    for (int i = 32; i < 64; i++) {
        float v = acc[i];
        #pragma unroll
        for (int off = 16; off; off >>= 1) v += __shfl_xor_sync(0xffffffffu, v, off);
        if (lane == i - 32) mine1 = v;
    }
    g_ac3[b][k][lane] = mine0;
    g_ac3[b][k][32 + lane] = mine1;
    if (lane == 0) g_cc3[b][k] = cf;
}

// ---------------- 10. fuse: concat -> GEMV -> BN -> relu ----------------
__global__ __launch_bounds__(128) void fuse_kernel(const float* __restrict__ Wf,
                                                   const float* __restrict__ gma,
                                                   const float* __restrict__ bta,
                                                   const float* __restrict__ mea,
                                                   const float* __restrict__ var,
                                                   float* __restrict__ out) {
    __shared__ float f[352];
    const int k = blockIdx.x, b = blockIdx.y, t = threadIdx.x;
    f[t] = g_bevf[b][k][t];
    f[128 + t] = g_bevf[b][k][128 + t];
    if (t < 32) {
        const float c = fmaxf(g_craw[b][k], 1.0f);
        f[256 + t] = __fdiv_rn(g_araw[b][k][t], c);
    } else if (t < 96) {
        const float c = fmaxf(g_cc3[b][k], 1.0f);
        f[256 + t] = __fdiv_rn(g_ac3[b][k][t - 32], c);
    }
    __syncthreads();
    float s = 0.f;
    #pragma unroll 8
    for (int c = 0; c < 352; c++) s = fmaf(f[c], Wf[c * 128 + t], s);
    const float bn = (s - mea[t]) * rsqrtf(var[t] + 1e-5f) * gma[t] + bta[t];
    out[((size_t)(b * KP + k)) * 128 + t] = fmaxf(bn, 0.f);
}

// ---------------- launcher ----------------
extern "C" void kernel_launch(void* const* d_in, const int* in_sizes, int n_in,
                              void* d_out, int out_size) {
    const float* points  = (const float*)d_in[0];
    const float* bboxes  = (const float*)d_in[1];
    const float* spatial = (const float*)d_in[2];
    const float* conv3   = (const float*)d_in[3];
    const float* W_raw   = (const float*)d_in[4];
    const float* b_raw   = (const float*)d_in[5];
    const float* W_c3    = (const float*)d_in[6];
    const float* b_c3    = (const float*)d_in[7];
    const float* W_fuse  = (const float*)d_in[8];
    const float* bn_g    = (const float*)d_in[9];
    const float* bn_b    = (const float*)d_in[10];
    const float* bn_m    = (const float*)d_in[11];
    const float* bn_v    = (const float*)d_in[12];
    float* out = (float*)d_out;

    const int main_elems = BB * KP * 128;
    float* out_kp = nullptr;
    if (out_size >= main_elems + BB * KP * 3) out_kp = out + (out_size - BB * KP * 3);

    const int fps_smem = 3 * NP * (int)sizeof(float) + 32 * 4 + 32 * 4 + 4 * 4;
    cudaFuncSetAttribute(fps_kernel, cudaFuncAttributeMaxDynamicSharedMemorySize, fps_smem);

    prep_points_kernel<<<dim3(NP / 256, BB), 256>>>(points, bboxes);
    sort_kernel<<<BB, 1024>>>();
    fps_kernel<<<BB, 1024, fps_smem>>>(out_kp);
    prep_c3_kernel<<<dim3(MP / 256, BB), 256>>>(conv3);
    transform_raw_kernel<<<dim3(NP / 8, BB), 256>>>(points, W_raw, b_raw);
    transform_c3_kernel<<<dim3(MP / 4, BB), 256>>>(conv3, W_c3, b_c3);
    transpose_bev_kernel<<<dim3((HW + 31) / 32, CB / 32, BB * HW), dim3(32, 8)>>>(spatial);
    bilinear_kernel<<<dim3(KP, BB), 256>>>();
    agg_raw_kernel<<<dim3(BB * KP / 8), 256>>>();
    agg_c3_kernel<<<dim3(BB * KP / 8), 256>>>();
    fuse_kernel<<<dim3(KP, BB), 128>>>(W_fuse, bn_g, bn_b, bn_m, bn_v, out);
}